// round 2
// baseline (speedup 1.0000x reference)
#include <cuda_runtime.h>
#include <cuda_bf16.h>
#include <math.h>

// Problem constants
#define Bsz   2
#define Npts  8192
#define Kn    3
#define NC    8              // candidate chunks
#define CHUNK (Npts / NC)    // 1024 candidates per chunk
#define TILE  128            // smem candidate tile / threads per block
#define QPT   4              // queries per thread
#define QPB   (TILE * QPT)   // 512 queries per block
#define NQ    (Bsz * Npts)   // 16384 total queries

typedef unsigned long long u64;

// Packed f32x2 helpers (sm_103a; ptxas won't auto-fuse these — must be PTX)
#define PACK_F32X2(out, lo, hi) \
    asm("mov.b64 %0, {%1, %2};" : "=l"(out) : "f"(lo), "f"(hi))
#define UNPACK_F32X2(lo, hi, in) \
    asm("mov.b64 {%0, %1}, %2;" : "=f"(lo), "=f"(hi) : "l"(in))
#define ADD_F32X2(out, a, b) \
    asm("add.rn.f32x2 %0, %1, %2;" : "=l"(out) : "l"(a), "l"(b))
#define MUL_F32X2(out, a, b) \
    asm("mul.rn.f32x2 %0, %1, %2;" : "=l"(out) : "l"(a), "l"(b))
#define FMA_F32X2(out, a, b, c) \
    asm("fma.rn.f32x2 %0, %1, %2, %3;" : "=l"(out) : "l"(a), "l"(b), "l"(c))

// Scratch: per (query, chunk) partial top-3 (dist + idx)
__device__ float g_pd[NQ * NC * 3];
__device__ int   g_pi[NQ * NC * 3];

// Top-3 insert, strict < while scanning ascending candidate index
// == jax.lax.top_k tie-break (smaller index wins on equal distance).
__device__ __forceinline__ void insert3(float f, int cand,
                                        float& d0, float& d1, float& d2,
                                        int& i0, int& i1, int& i2)
{
    if (f < d2) {
        if (f < d0)      { d2 = d1; i2 = i1; d1 = d0; i1 = i0; d0 = f; i0 = cand; }
        else if (f < d1) { d2 = d1; i2 = i1; d1 = f;  i1 = cand; }
        else             { d2 = f;  i2 = cand; }
    }
}

// ---------------------------------------------------------------------------
// Kernel 1: partial KNN. blockIdx.x = query tile (512 queries), blockIdx.y =
// chunk. Each thread owns 4 queries packed as 2 f32x2 pairs; candidates are
// staged in smem negated+duplicated so one LDS.64 feeds the packed add.
// ---------------------------------------------------------------------------
__global__ __launch_bounds__(TILE) void knn_partial_kernel(const float* __restrict__ xyz)
{
    const int tid   = threadIdx.x;
    const int qbase = blockIdx.x * QPB;        // first global query of this block
    const int b     = qbase >> 13;             // 512 | 8192, so one batch per block
    const float* xb = xyz + (size_t)b * Npts * 3;
    const int q0    = (qbase & (Npts - 1)) + tid;   // queries q0 + i*128

    // Load & pack 4 queries: (0,1) and (2,3)
    float qx[QPT], qy[QPT], qz[QPT];
    #pragma unroll
    for (int i = 0; i < QPT; i++) {
        const int q = q0 + i * TILE;
        qx[i] = xb[q * 3 + 0];
        qy[i] = xb[q * 3 + 1];
        qz[i] = xb[q * 3 + 2];
    }
    u64 qx01, qy01, qz01, qx23, qy23, qz23;
    PACK_F32X2(qx01, qx[0], qx[1]); PACK_F32X2(qx23, qx[2], qx[3]);
    PACK_F32X2(qy01, qy[0], qy[1]); PACK_F32X2(qy23, qy[2], qy[3]);
    PACK_F32X2(qz01, qz[0], qz[1]); PACK_F32X2(qz23, qz[2], qz[3]);

    // Per-query top-3 state (fully unrolled constant indices -> registers)
    float d0[QPT], d1[QPT], d2[QPT];
    int   i0[QPT], i1[QPT], i2[QPT];
    #pragma unroll
    for (int i = 0; i < QPT; i++) {
        d0[i] = d1[i] = d2[i] = INFINITY;
        i0[i] = i1[i] = i2[i] = 0x7fffffff;
    }

    __shared__ float2 snx[TILE], sny[TILE], snz[TILE];   // {-s, -s} duplicated

    const int cbeg = blockIdx.y * CHUNK;
    const int cend = cbeg + CHUNK;

    for (int t0 = cbeg; t0 < cend; t0 += TILE) {
        __syncthreads();
        {
            const int j = t0 + tid;
            const float x = xb[j * 3 + 0];
            const float y = xb[j * 3 + 1];
            const float z = xb[j * 3 + 2];
            snx[tid] = make_float2(-x, -x);
            sny[tid] = make_float2(-y, -y);
            snz[tid] = make_float2(-z, -z);
        }
        __syncthreads();

        #pragma unroll 8
        for (int jj = 0; jj < TILE; jj++) {
            const u64 nx = *reinterpret_cast<const u64*>(&snx[jj]);
            const u64 ny = *reinterpret_cast<const u64*>(&sny[jj]);
            const u64 nz = *reinterpret_cast<const u64*>(&snz[jj]);

            u64 dx, dy, dz, t01, t23;
            // queries 0,1
            ADD_F32X2(dx, qx01, nx);
            ADD_F32X2(dy, qy01, ny);
            ADD_F32X2(dz, qz01, nz);
            MUL_F32X2(t01, dz, dz);
            FMA_F32X2(t01, dy, dy, t01);
            FMA_F32X2(t01, dx, dx, t01);
            // queries 2,3
            ADD_F32X2(dx, qx23, nx);
            ADD_F32X2(dy, qy23, ny);
            ADD_F32X2(dz, qz23, nz);
            MUL_F32X2(t23, dz, dz);
            FMA_F32X2(t23, dy, dy, t23);
            FMA_F32X2(t23, dx, dx, t23);

            float f0, f1, f2, f3;
            UNPACK_F32X2(f0, f1, t01);
            UNPACK_F32X2(f2, f3, t23);

            const int cand = t0 + jj;
            insert3(f0, cand, d0[0], d1[0], d2[0], i0[0], i1[0], i2[0]);
            insert3(f1, cand, d0[1], d1[1], d2[1], i0[1], i1[1], i2[1]);
            insert3(f2, cand, d0[2], d1[2], d2[2], i0[2], i1[2], i2[2]);
            insert3(f3, cand, d0[3], d1[3], d2[3], i0[3], i1[3], i2[3]);
        }
    }

    const int ch = blockIdx.y;
    #pragma unroll
    for (int i = 0; i < QPT; i++) {
        const int gq   = qbase + i * TILE + tid;
        const int base = (gq * NC + ch) * 3;
        g_pd[base + 0] = d0[i]; g_pd[base + 1] = d1[i]; g_pd[base + 2] = d2[i];
        g_pi[base + 0] = i0[i]; g_pi[base + 1] = i1[i]; g_pi[base + 2] = i2[i];
    }
}

// ---------------------------------------------------------------------------
// Kernel 2: merge partials (warp per query) + gather attributes + std loss.
// ---------------------------------------------------------------------------
#define K2_THREADS 256
#define K2_WARPS   (K2_THREADS / 32)

__global__ __launch_bounds__(K2_THREADS) void merge_loss_kernel(
    const float* __restrict__ rot,  // [B,N,4]
    const float* __restrict__ scl,  // [B,N,3]
    const float* __restrict__ col,  // [B,N,45]
    const float* __restrict__ opa,  // [B,N,1]
    float* __restrict__ out)
{
    const int lane = threadIdx.x & 31;
    const int wid  = threadIdx.x >> 5;
    const int gq   = blockIdx.x * K2_WARPS + wid;
    const int b    = gq >> 13;

    float v  = INFINITY;
    int   ix = 0x7fffffff;
    if (lane < NC * 3) {
        v  = g_pd[gq * (NC * 3) + lane];
        ix = g_pi[gq * (NC * 3) + lane];
    }

    // 3 rounds of warp lexicographic argmin (d, then idx)
    float nd[Kn];
    int   ni[Kn];
    #pragma unroll
    for (int r = 0; r < Kn; r++) {
        float bv = v; int bi = ix;
        #pragma unroll
        for (int off = 16; off > 0; off >>= 1) {
            const float ov = __shfl_xor_sync(0xffffffffu, bv, off);
            const int   oi = __shfl_xor_sync(0xffffffffu, bi, off);
            if (ov < bv || (ov == bv && oi < bi)) { bv = ov; bi = oi; }
        }
        nd[r] = bv; ni[r] = bi;
        if (ix == bi) v = INFINITY;
    }

    const int r0 = b * Npts + ni[0];
    const int r1 = b * Npts + ni[1];
    const int r2 = b * Npts + ni[2];

    float local = 0.0f;
    if (lane == 0)
        local += (nd[0] + nd[1] + nd[2]) * (1.0f / ((float)Bsz * Npts * Kn));

    // 53 channels: 0..3 rot(C=4), 4..6 scales(C=3), 7 opacity(C=1), 8..52 colors(C=45)
    for (int c = lane; c < 53; c += 32) {
        const float* bp; int C; int cc;
        if (c < 4)       { bp = rot; C = 4;  cc = c;     }
        else if (c < 7)  { bp = scl; C = 3;  cc = c - 4; }
        else if (c < 8)  { bp = opa; C = 1;  cc = 0;     }
        else             { bp = col; C = 45; cc = c - 8; }

        const float x0 = __ldg(bp + (size_t)r0 * C + cc);
        const float x1 = __ldg(bp + (size_t)r1 * C + cc);
        const float x2 = __ldg(bp + (size_t)r2 * C + cc);

        const float m  = (x0 + x1 + x2) * (1.0f / 3.0f);
        const float e0 = x0 - m, e1 = x1 - m, e2 = x2 - m;
        const float var = fmaf(e0, e0, fmaf(e1, e1, e2 * e2)) * 0.5f;  // ddof=1
        local += sqrtf(var) * (1.0f / ((float)Bsz * Npts * (float)C));
    }

    #pragma unroll
    for (int off = 16; off > 0; off >>= 1)
        local += __shfl_xor_sync(0xffffffffu, local, off);

    __shared__ float red[K2_WARPS];
    if (lane == 0) red[wid] = local;
    __syncthreads();

    if (threadIdx.x < K2_WARPS) {
        float s = red[threadIdx.x];
        #pragma unroll
        for (int off = K2_WARPS / 2; off > 0; off >>= 1)
            s += __shfl_xor_sync((1u << K2_WARPS) - 1u, s, off);
        if (threadIdx.x == 0) atomicAdd(out, s);
    }
}

__global__ void zero_out_kernel(float* out) { out[0] = 0.0f; }

// ---------------------------------------------------------------------------
extern "C" void kernel_launch(void* const* d_in, const int* in_sizes, int n_in,
                              void* d_out, int out_size)
{
    const float* xyz = (const float*)d_in[0];
    const float* rot = (const float*)d_in[1];
    const float* scl = (const float*)d_in[2];
    const float* col = (const float*)d_in[3];
    const float* opa = (const float*)d_in[4];
    float* out = (float*)d_out;

    zero_out_kernel<<<1, 1>>>(out);

    dim3 g1(NQ / QPB, NC);   // (32, 8) = 256 blocks
    knn_partial_kernel<<<g1, TILE>>>(xyz);

    merge_loss_kernel<<<NQ / K2_WARPS, K2_THREADS>>>(rot, scl, col, opa, out);
}

// round 3
// speedup vs baseline: 1.3920x; 1.3920x over previous
#include <cuda_runtime.h>
#include <cuda_bf16.h>
#include <math.h>

// Problem constants
#define Bsz   2
#define Npts  8192
#define Kn    3
#define NC    32             // candidate chunks (occupancy knob)
#define CHUNK (Npts / NC)    // 256 candidates per chunk
#define TILE  128            // smem candidate tile / threads per block
#define QPT   4              // queries per thread
#define QPB   (TILE * QPT)   // 512 queries per block
#define NQ    (Bsz * Npts)   // 16384 total queries

typedef unsigned long long u64;

// Packed f32x2 helpers (sm_103a; must come from PTX)
#define PACK_F32X2(out, lo, hi) \
    asm("mov.b64 %0, {%1, %2};" : "=l"(out) : "f"(lo), "f"(hi))
#define UNPACK_F32X2(lo, hi, in) \
    asm("mov.b64 {%0, %1}, %2;" : "=f"(lo), "=f"(hi) : "l"(in))
#define ADD_F32X2(out, a, b) \
    asm("add.rn.f32x2 %0, %1, %2;" : "=l"(out) : "l"(a), "l"(b))
#define MUL_F32X2(out, a, b) \
    asm("mul.rn.f32x2 %0, %1, %2;" : "=l"(out) : "l"(a), "l"(b))
#define FMA_F32X2(out, a, b, c) \
    asm("fma.rn.f32x2 %0, %1, %2, %3;" : "=l"(out) : "l"(a), "l"(b), "l"(c))

// Scratch: per (query, chunk) partial top-3 (dist + idx)
__device__ float g_pd[NQ * NC * 3];
__device__ int   g_pi[NQ * NC * 3];

// Top-3 insert, strict < while scanning ascending candidate index
// == jax.lax.top_k tie-break (smaller index wins on equal distance).
__device__ __forceinline__ void insert3(float f, int cand,
                                        float& d0, float& d1, float& d2,
                                        int& i0, int& i1, int& i2)
{
    if (f < d2) {
        if (f < d0)      { d2 = d1; i2 = i1; d1 = d0; i1 = i0; d0 = f; i0 = cand; }
        else if (f < d1) { d2 = d1; i2 = i1; d1 = f;  i1 = cand; }
        else             { d2 = f;  i2 = cand; }
    }
}

// ---------------------------------------------------------------------------
// Kernel 1: partial KNN. blockIdx.x = query tile (512 queries), blockIdx.y =
// chunk (32 chunks of 256 candidates). Each thread owns 4 queries packed as
// 2 f32x2 pairs; candidates staged in smem negated+duplicated so one LDS.64
// feeds the packed add directly.
// ---------------------------------------------------------------------------
__global__ __launch_bounds__(TILE) void knn_partial_kernel(const float* __restrict__ xyz)
{
    const int tid   = threadIdx.x;
    const int qbase = blockIdx.x * QPB;
    const int b     = qbase >> 13;             // 512 | 8192 -> one batch per block
    const float* xb = xyz + (size_t)b * Npts * 3;
    const int q0    = (qbase & (Npts - 1)) + tid;

    float qx[QPT], qy[QPT], qz[QPT];
    #pragma unroll
    for (int i = 0; i < QPT; i++) {
        const int q = q0 + i * TILE;
        qx[i] = xb[q * 3 + 0];
        qy[i] = xb[q * 3 + 1];
        qz[i] = xb[q * 3 + 2];
    }
    u64 qx01, qy01, qz01, qx23, qy23, qz23;
    PACK_F32X2(qx01, qx[0], qx[1]); PACK_F32X2(qx23, qx[2], qx[3]);
    PACK_F32X2(qy01, qy[0], qy[1]); PACK_F32X2(qy23, qy[2], qy[3]);
    PACK_F32X2(qz01, qz[0], qz[1]); PACK_F32X2(qz23, qz[2], qz[3]);

    float d0[QPT], d1[QPT], d2[QPT];
    int   i0[QPT], i1[QPT], i2[QPT];
    #pragma unroll
    for (int i = 0; i < QPT; i++) {
        d0[i] = d1[i] = d2[i] = INFINITY;
        i0[i] = i1[i] = i2[i] = 0x7fffffff;
    }

    __shared__ float2 snx[TILE], sny[TILE], snz[TILE];   // {-s, -s} duplicated

    const int cbeg = blockIdx.y * CHUNK;
    const int cend = cbeg + CHUNK;

    for (int t0 = cbeg; t0 < cend; t0 += TILE) {
        __syncthreads();
        {
            const int j = t0 + tid;
            const float x = xb[j * 3 + 0];
            const float y = xb[j * 3 + 1];
            const float z = xb[j * 3 + 2];
            snx[tid] = make_float2(-x, -x);
            sny[tid] = make_float2(-y, -y);
            snz[tid] = make_float2(-z, -z);
        }
        __syncthreads();

        #pragma unroll 8
        for (int jj = 0; jj < TILE; jj++) {
            const u64 nx = *reinterpret_cast<const u64*>(&snx[jj]);
            const u64 ny = *reinterpret_cast<const u64*>(&sny[jj]);
            const u64 nz = *reinterpret_cast<const u64*>(&snz[jj]);

            u64 dx, dy, dz, t01, t23;
            ADD_F32X2(dx, qx01, nx);
            ADD_F32X2(dy, qy01, ny);
            ADD_F32X2(dz, qz01, nz);
            MUL_F32X2(t01, dz, dz);
            FMA_F32X2(t01, dy, dy, t01);
            FMA_F32X2(t01, dx, dx, t01);
            ADD_F32X2(dx, qx23, nx);
            ADD_F32X2(dy, qy23, ny);
            ADD_F32X2(dz, qz23, nz);
            MUL_F32X2(t23, dz, dz);
            FMA_F32X2(t23, dy, dy, t23);
            FMA_F32X2(t23, dx, dx, t23);

            float f0, f1, f2, f3;
            UNPACK_F32X2(f0, f1, t01);
            UNPACK_F32X2(f2, f3, t23);

            const int cand = t0 + jj;
            insert3(f0, cand, d0[0], d1[0], d2[0], i0[0], i1[0], i2[0]);
            insert3(f1, cand, d0[1], d1[1], d2[1], i0[1], i1[1], i2[1]);
            insert3(f2, cand, d0[2], d1[2], d2[2], i0[2], i1[2], i2[2]);
            insert3(f3, cand, d0[3], d1[3], d2[3], i0[3], i1[3], i2[3]);
        }
    }

    const int ch = blockIdx.y;
    #pragma unroll
    for (int i = 0; i < QPT; i++) {
        const int gq   = qbase + i * TILE + tid;
        const int base = (gq * NC + ch) * 3;
        g_pd[base + 0] = d0[i]; g_pd[base + 1] = d1[i]; g_pd[base + 2] = d2[i];
        g_pi[base + 0] = i0[i]; g_pi[base + 1] = i1[i]; g_pi[base + 2] = i2[i];
    }
}

// ---------------------------------------------------------------------------
// Kernel 2: merge partials (warp per query, 3 slots per lane = 96 partials)
// + gather attributes + std loss.
// ---------------------------------------------------------------------------
#define K2_THREADS 256
#define K2_WARPS   (K2_THREADS / 32)
#define NPART      (NC * 3)          // 96 partials per query
#define SLOTS      (NPART / 32)      // 3 per lane

__global__ __launch_bounds__(K2_THREADS) void merge_loss_kernel(
    const float* __restrict__ rot,  // [B,N,4]
    const float* __restrict__ scl,  // [B,N,3]
    const float* __restrict__ col,  // [B,N,45]
    const float* __restrict__ opa,  // [B,N,1]
    float* __restrict__ out)
{
    const int lane = threadIdx.x & 31;
    const int wid  = threadIdx.x >> 5;
    const int gq   = blockIdx.x * K2_WARPS + wid;
    const int b    = gq >> 13;

    // Each lane holds SLOTS=3 partial candidates (coalesced: 96 consecutive)
    float v[SLOTS]; int ix[SLOTS];
    {
        const int base = gq * NPART + lane * SLOTS;
        #pragma unroll
        for (int s = 0; s < SLOTS; s++) {
            v[s]  = g_pd[base + s];
            ix[s] = g_pi[base + s];
        }
    }

    // 3 rounds of lexicographic argmin (d, then idx) across 96 candidates.
    float nd[Kn];
    int   ni[Kn];
    #pragma unroll
    for (int r = 0; r < Kn; r++) {
        float bv = v[0]; int bi = ix[0];
        #pragma unroll
        for (int s = 1; s < SLOTS; s++)
            if (v[s] < bv || (v[s] == bv && ix[s] < bi)) { bv = v[s]; bi = ix[s]; }
        #pragma unroll
        for (int off = 16; off > 0; off >>= 1) {
            const float ov = __shfl_xor_sync(0xffffffffu, bv, off);
            const int   oi = __shfl_xor_sync(0xffffffffu, bi, off);
            if (ov < bv || (ov == bv && oi < bi)) { bv = ov; bi = oi; }
        }
        nd[r] = bv; ni[r] = bi;
        #pragma unroll
        for (int s = 0; s < SLOTS; s++)
            if (ix[s] == bi) v[s] = INFINITY;   // indices unique across partials
    }

    const int r0 = b * Npts + ni[0];
    const int r1 = b * Npts + ni[1];
    const int r2 = b * Npts + ni[2];

    float local = 0.0f;
    if (lane == 0)
        local += (nd[0] + nd[1] + nd[2]) * (1.0f / ((float)Bsz * Npts * Kn));

    // 53 channels: 0..3 rot(C=4), 4..6 scales(C=3), 7 opacity(C=1), 8..52 colors(C=45)
    for (int c = lane; c < 53; c += 32) {
        const float* bp; int C; int cc;
        if (c < 4)       { bp = rot; C = 4;  cc = c;     }
        else if (c < 7)  { bp = scl; C = 3;  cc = c - 4; }
        else if (c < 8)  { bp = opa; C = 1;  cc = 0;     }
        else             { bp = col; C = 45; cc = c - 8; }

        const float x0 = __ldg(bp + (size_t)r0 * C + cc);
        const float x1 = __ldg(bp + (size_t)r1 * C + cc);
        const float x2 = __ldg(bp + (size_t)r2 * C + cc);

        const float m  = (x0 + x1 + x2) * (1.0f / 3.0f);
        const float e0 = x0 - m, e1 = x1 - m, e2 = x2 - m;
        const float var = fmaf(e0, e0, fmaf(e1, e1, e2 * e2)) * 0.5f;  // ddof=1
        local += sqrtf(var) * (1.0f / ((float)Bsz * Npts * (float)C));
    }

    #pragma unroll
    for (int off = 16; off > 0; off >>= 1)
        local += __shfl_xor_sync(0xffffffffu, local, off);

    __shared__ float red[K2_WARPS];
    if (lane == 0) red[wid] = local;
    __syncthreads();

    if (threadIdx.x < K2_WARPS) {
        float s = red[threadIdx.x];
        #pragma unroll
        for (int off = K2_WARPS / 2; off > 0; off >>= 1)
            s += __shfl_xor_sync((1u << K2_WARPS) - 1u, s, off);
        if (threadIdx.x == 0) atomicAdd(out, s);
    }
}

__global__ void zero_out_kernel(float* out) { out[0] = 0.0f; }

// ---------------------------------------------------------------------------
extern "C" void kernel_launch(void* const* d_in, const int* in_sizes, int n_in,
                              void* d_out, int out_size)
{
    const float* xyz = (const float*)d_in[0];
    const float* rot = (const float*)d_in[1];
    const float* scl = (const float*)d_in[2];
    const float* col = (const float*)d_in[3];
    const float* opa = (const float*)d_in[4];
    float* out = (float*)d_out;

    zero_out_kernel<<<1, 1>>>(out);

    dim3 g1(NQ / QPB, NC);   // (32, 32) = 1024 blocks, 27.7 warps/SM
    knn_partial_kernel<<<g1, TILE>>>(xyz);

    merge_loss_kernel<<<NQ / K2_WARPS, K2_THREADS>>>(rot, scl, col, opa, out);
}

// round 4
// speedup vs baseline: 1.6391x; 1.1775x over previous
#include <cuda_runtime.h>
#include <cuda_bf16.h>
#include <math.h>

// Problem constants
#define Bsz   2
#define Npts  8192
#define Kn    3
#define NC    16             // candidate chunks (occupancy knob)
#define CHUNK (Npts / NC)    // 512 candidates per chunk
#define TILE  128            // smem candidate tile / threads per block
#define QPT   2              // queries per thread
#define QPB   (TILE * QPT)   // 256 queries per block
#define NQ    (Bsz * Npts)   // 16384 total queries

// Scratch: per (query, chunk) partial top-3 (dist + idx)
__device__ float g_pd[NQ * NC * 3];
__device__ int   g_pi[NQ * NC * 3];

// Top-3 insert, strict < while scanning ascending candidate index
// == jax.lax.top_k tie-break (smaller index wins on equal distance).
__device__ __forceinline__ void insert3(float f, int cand,
                                        float& t0, float& t1, float& t2,
                                        int& i0, int& i1, int& i2)
{
    if (f < t2) {
        if (f < t0)      { t2 = t1; i2 = i1; t1 = t0; i1 = i0; t0 = f; i0 = cand; }
        else if (f < t1) { t2 = t1; i2 = i1; t1 = f;  i1 = cand; }
        else             { t2 = f;  i2 = cand; }
    }
}

// ---------------------------------------------------------------------------
// Kernel 1: partial KNN in t-space.  d = |q|^2 + |s|^2 - 2 q.s ;
// t = d - |q|^2 = (-2s).q + |s|^2 is monotone in d for a fixed query, so the
// top-3 scan runs on t (3 FFMA + 1 compare per pair). Candidates staged in
// smem as float4 {-2x,-2y,-2z,|s|^2}: ONE broadcast LDS.128 per candidate.
// blockIdx.x = query tile (256 queries), blockIdx.y = chunk (512 candidates).
// Block (0,0) thread 0 also zeroes the output accumulator.
// ---------------------------------------------------------------------------
__global__ __launch_bounds__(TILE) void knn_partial_kernel(
    const float* __restrict__ xyz, float* __restrict__ out)
{
    if (blockIdx.x == 0 && blockIdx.y == 0 && threadIdx.x == 0) out[0] = 0.0f;

    const int tid   = threadIdx.x;
    const int qbase = blockIdx.x * QPB;
    const int b     = qbase >> 13;            // 256 | 8192 -> one batch per block
    const float* xb = xyz + (size_t)b * Npts * 3;
    const int q0    = (qbase & (Npts - 1)) + tid;

    // Load queries + their squared norms
    float qx[QPT], qy[QPT], qz[QPT], qn[QPT];
    #pragma unroll
    for (int i = 0; i < QPT; i++) {
        const int q = q0 + i * TILE;
        qx[i] = xb[q * 3 + 0];
        qy[i] = xb[q * 3 + 1];
        qz[i] = xb[q * 3 + 2];
        qn[i] = fmaf(qx[i], qx[i], fmaf(qy[i], qy[i], qz[i] * qz[i]));
    }

    // Top-3 state in t-space
    float t0v[QPT], t1v[QPT], t2v[QPT];
    int   i0[QPT], i1[QPT], i2[QPT];
    #pragma unroll
    for (int i = 0; i < QPT; i++) {
        t0v[i] = t1v[i] = t2v[i] = INFINITY;
        i0[i] = i1[i] = i2[i] = 0x7fffffff;
    }

    __shared__ float4 sc[TILE];   // {-2x, -2y, -2z, |s|^2}

    const int cbeg = blockIdx.y * CHUNK;
    const int cend = cbeg + CHUNK;

    for (int t0 = cbeg; t0 < cend; t0 += TILE) {
        __syncthreads();
        {
            const int j = t0 + tid;
            const float x = xb[j * 3 + 0];
            const float y = xb[j * 3 + 1];
            const float z = xb[j * 3 + 2];
            const float n = fmaf(x, x, fmaf(y, y, z * z));
            sc[tid] = make_float4(-2.0f * x, -2.0f * y, -2.0f * z, n);
        }
        __syncthreads();

        #pragma unroll 8
        for (int jj = 0; jj < TILE; jj++) {
            const float4 c = sc[jj];            // broadcast LDS.128
            const int cand = t0 + jj;
            #pragma unroll
            for (int i = 0; i < QPT; i++) {
                float t = fmaf(qx[i], c.x, c.w);
                t = fmaf(qy[i], c.y, t);
                t = fmaf(qz[i], c.z, t);
                insert3(t, cand, t0v[i], t1v[i], t2v[i], i0[i], i1[i], i2[i]);
            }
        }
    }

    // Convert t -> d = t + |q|^2 at writeout
    const int ch = blockIdx.y;
    #pragma unroll
    for (int i = 0; i < QPT; i++) {
        const int gq   = qbase + i * TILE + tid;
        const int base = (gq * NC + ch) * 3;
        g_pd[base + 0] = t0v[i] + qn[i];
        g_pd[base + 1] = t1v[i] + qn[i];
        g_pd[base + 2] = t2v[i] + qn[i];
        g_pi[base + 0] = i0[i]; g_pi[base + 1] = i1[i]; g_pi[base + 2] = i2[i];
    }
}

// ---------------------------------------------------------------------------
// Kernel 2: merge partials (warp per query, 48 partials = 2 slots on lanes
// 0..23) + gather attributes + std loss.
// ---------------------------------------------------------------------------
#define K2_THREADS 256
#define K2_WARPS   (K2_THREADS / 32)
#define NPART      (NC * 3)          // 48 partials per query
#define SLOTS      2                 // 2 per lane on lanes 0..23

__global__ __launch_bounds__(K2_THREADS) void merge_loss_kernel(
    const float* __restrict__ rot,  // [B,N,4]
    const float* __restrict__ scl,  // [B,N,3]
    const float* __restrict__ col,  // [B,N,45]
    const float* __restrict__ opa,  // [B,N,1]
    float* __restrict__ out)
{
    const int lane = threadIdx.x & 31;
    const int wid  = threadIdx.x >> 5;
    const int gq   = blockIdx.x * K2_WARPS + wid;
    const int b    = gq >> 13;

    float v[SLOTS]; int ix[SLOTS];
    #pragma unroll
    for (int s = 0; s < SLOTS; s++) { v[s] = INFINITY; ix[s] = 0x7fffffff; }
    if (lane < NPART / SLOTS) {
        const int base = gq * NPART + lane * SLOTS;
        #pragma unroll
        for (int s = 0; s < SLOTS; s++) {
            v[s]  = g_pd[base + s];
            ix[s] = g_pi[base + s];
        }
    }

    // 3 rounds of lexicographic argmin (d, then idx) across 48 candidates.
    float nd[Kn];
    int   ni[Kn];
    #pragma unroll
    for (int r = 0; r < Kn; r++) {
        float bv = v[0]; int bi = ix[0];
        #pragma unroll
        for (int s = 1; s < SLOTS; s++)
            if (v[s] < bv || (v[s] == bv && ix[s] < bi)) { bv = v[s]; bi = ix[s]; }
        #pragma unroll
        for (int off = 16; off > 0; off >>= 1) {
            const float ov = __shfl_xor_sync(0xffffffffu, bv, off);
            const int   oi = __shfl_xor_sync(0xffffffffu, bi, off);
            if (ov < bv || (ov == bv && oi < bi)) { bv = ov; bi = oi; }
        }
        nd[r] = bv; ni[r] = bi;
        #pragma unroll
        for (int s = 0; s < SLOTS; s++)
            if (ix[s] == bi) v[s] = INFINITY;   // indices unique across partials
    }

    const int r0 = b * Npts + ni[0];
    const int r1 = b * Npts + ni[1];
    const int r2 = b * Npts + ni[2];

    float local = 0.0f;
    if (lane == 0)
        local += (nd[0] + nd[1] + nd[2]) * (1.0f / ((float)Bsz * Npts * Kn));

    // 53 channels: 0..3 rot(C=4), 4..6 scales(C=3), 7 opacity(C=1), 8..52 colors(C=45)
    for (int c = lane; c < 53; c += 32) {
        const float* bp; int C; int cc;
        if (c < 4)       { bp = rot; C = 4;  cc = c;     }
        else if (c < 7)  { bp = scl; C = 3;  cc = c - 4; }
        else if (c < 8)  { bp = opa; C = 1;  cc = 0;     }
        else             { bp = col; C = 45; cc = c - 8; }

        const float x0 = __ldg(bp + (size_t)r0 * C + cc);
        const float x1 = __ldg(bp + (size_t)r1 * C + cc);
        const float x2 = __ldg(bp + (size_t)r2 * C + cc);

        const float m  = (x0 + x1 + x2) * (1.0f / 3.0f);
        const float e0 = x0 - m, e1 = x1 - m, e2 = x2 - m;
        const float var = fmaf(e0, e0, fmaf(e1, e1, e2 * e2)) * 0.5f;  // ddof=1
        local += sqrtf(var) * (1.0f / ((float)Bsz * Npts * (float)C));
    }

    #pragma unroll
    for (int off = 16; off > 0; off >>= 1)
        local += __shfl_xor_sync(0xffffffffu, local, off);

    __shared__ float red[K2_WARPS];
    if (lane == 0) red[wid] = local;
    __syncthreads();

    if (threadIdx.x < K2_WARPS) {
        float s = red[threadIdx.x];
        #pragma unroll
        for (int off = K2_WARPS / 2; off > 0; off >>= 1)
            s += __shfl_xor_sync((1u << K2_WARPS) - 1u, s, off);
        if (threadIdx.x == 0) atomicAdd(out, s);
    }
}

// ---------------------------------------------------------------------------
extern "C" void kernel_launch(void* const* d_in, const int* in_sizes, int n_in,
                              void* d_out, int out_size)
{
    const float* xyz = (const float*)d_in[0];
    const float* rot = (const float*)d_in[1];
    const float* scl = (const float*)d_in[2];
    const float* col = (const float*)d_in[3];
    const float* opa = (const float*)d_in[4];
    float* out = (float*)d_out;

    dim3 g1(NQ / QPB, NC);   // (64, 16) = 1024 blocks, ~28 warps/SM
    knn_partial_kernel<<<g1, TILE>>>(xyz, out);

    merge_loss_kernel<<<NQ / K2_WARPS, K2_THREADS>>>(rot, scl, col, opa, out);
}